// round 15
// baseline (speedup 1.0000x reference)
#include <cuda_runtime.h>
#include <cuda_fp16.h>
#include <stdint.h>
#include <math.h>

#define B    16
#define VN   256
#define QN   256
#define VD   512
#define QD   768
#define HK   1536
#define HOUT 8
#define HD   512
#define KP   3

// ---------------- scratch (device globals) ----------------------------------
__device__ __half g_vh[B * VN * HK];               // v_ fp16
__device__ __half g_qh[B * QN * HK];               // q_ fp16
__device__ __half g_ssh[B * VN * QN];              // S fp16
__device__ float g_lk[B * HK];
__device__ __half g_hwh[(HOUT + 1) * HK];          // 8 head rows + sum row
__device__ float g_hbsum;
__device__ unsigned char g_vmask[B * VN];
__device__ unsigned char g_qmask[B * QN];
__device__ __half g_vsh[B * VN * VD];
__device__ __half g_qsh[B * QN * QD];
__device__ __half g_wvh[HK * VD];
__device__ __half g_wqh[HK * QD];

static __device__ __forceinline__ uint32_t smem_u32(const void* p) {
    uint32_t a;
    asm("{ .reg .u64 t; cvta.to.shared.u64 t, %1; cvt.u32.u64 %0, t; }"
        : "=r"(a) : "l"(p));
    return a;
}

#define LDMX4(d, addr) \
    asm volatile("ldmatrix.sync.aligned.m8n8.x4.shared.b16 {%0,%1,%2,%3}, [%4];" \
                 : "=r"((d)[0]), "=r"((d)[1]), "=r"((d)[2]), "=r"((d)[3]) \
                 : "r"(addr))

#define LDMX4T(d, addr) \
    asm volatile("ldmatrix.sync.aligned.m8n8.x4.trans.shared.b16 {%0,%1,%2,%3}, [%4];" \
                 : "=r"((d)[0]), "=r"((d)[1]), "=r"((d)[2]), "=r"((d)[3]) \
                 : "r"(addr))

#define MMA16816(c, a, b0, b1) \
    asm volatile("mma.sync.aligned.m16n8k16.row.col.f32.f16.f16.f32 " \
                 "{%0,%1,%2,%3}, {%4,%5,%6,%7}, {%8,%9}, {%0,%1,%2,%3};" \
                 : "+f"((c)[0]), "+f"((c)[1]), "+f"((c)[2]), "+f"((c)[3]) \
                 : "r"((a)[0]), "r"((a)[1]), "r"((a)[2]), "r"((a)[3]), \
                   "r"(b0), "r"(b1))

#define CP16(dst, src) \
    asm volatile("cp.async.cg.shared.global [%0], [%1], 16;" \
                 :: "r"(dst), "l"(src))
#define CP_COMMIT() asm volatile("cp.async.commit_group;" ::: "memory")
#define CP_WAIT0()  asm volatile("cp.async.wait_group 0;" ::: "memory")
#define CP_WAIT1()  asm volatile("cp.async.wait_group 1;" ::: "memory")

static __device__ __forceinline__ uint32_t pack2h(float a, float b) {
    __half2 h = __floats2half2_rn(a, b);
    return *(uint32_t*)&h;
}

// ---------------- fused prep -------------------------------------------------
__global__ void prep_kernel(const float* __restrict__ v, const float* __restrict__ q,
                            const float* __restrict__ Wv, const float* __restrict__ Wq,
                            const float* __restrict__ h_mat,
                            const float* __restrict__ h_bias) {
    const int bid = blockIdx.x;
    const int tid = threadIdx.x;
    if (bid < 512) {
        int wid = tid >> 5, lane = tid & 31;
        int row = bid * 8 + wid;
        const float4* src = (const float4*)(v + (size_t)row * VD);
        uint2* dst = (uint2*)(g_vsh + (size_t)row * VD);
        float s = 0.f;
#pragma unroll
        for (int j = 0; j < 4; j++) {
            float4 x = src[j * 32 + lane];
            s += fabsf(x.x) + fabsf(x.y) + fabsf(x.z) + fabsf(x.w);
            uint2 h;
            h.x = pack2h(x.x, x.y);
            h.y = pack2h(x.z, x.w);
            dst[j * 32 + lane] = h;
        }
        for (int o = 16; o; o >>= 1) s += __shfl_xor_sync(0xffffffffu, s, o);
        if (lane == 0) g_vmask[row] = (s == 0.f) ? 1 : 0;
    } else if (bid < 1024) {
        int wid = tid >> 5, lane = tid & 31;
        int row = (bid - 512) * 8 + wid;
        const float4* src = (const float4*)(q + (size_t)row * QD);
        uint2* dst = (uint2*)(g_qsh + (size_t)row * QD);
        float s = 0.f;
#pragma unroll
        for (int j = 0; j < 6; j++) {
            float4 x = src[j * 32 + lane];
            s += fabsf(x.x) + fabsf(x.y) + fabsf(x.z) + fabsf(x.w);
            uint2 h;
            h.x = pack2h(x.x, x.y);
            h.y = pack2h(x.z, x.w);
            dst[j * 32 + lane] = h;
        }
        for (int o = 16; o; o >>= 1) s += __shfl_xor_sync(0xffffffffu, s, o);
        if (lane == 0) g_qmask[row] = (s == 0.f) ? 1 : 0;
    } else if (bid < 1216) {
        int base = (bid - 1024) * 1024;
#pragma unroll
        for (int j = 0; j < 4; j++) {
            int i = base + j * 256 + tid;
            float4 x = ((const float4*)Wv)[i];
            uint2 h;
            h.x = pack2h(x.x, x.y);
            h.y = pack2h(x.z, x.w);
            *(uint2*)(g_wvh + (size_t)i * 4) = h;
        }
    } else if (bid < 1504) {
        int base = (bid - 1216) * 1024;
#pragma unroll
        for (int j = 0; j < 4; j++) {
            int i = base + j * 256 + tid;
            float4 x = ((const float4*)Wq)[i];
            uint2 h;
            h.x = pack2h(x.x, x.y);
            h.y = pack2h(x.z, x.w);
            *(uint2*)(g_wqh + (size_t)i * 4) = h;
        }
    } else if (bid == 1504) {
        for (int k = tid; k < HK; k += 256) {
            float s = 0.f;
#pragma unroll
            for (int h = 0; h < HOUT; h++) {
                float w = h_mat[h * HK + k];
                g_hwh[h * HK + k] = __float2half_rn(w);
                s += w;
            }
            g_hwh[HOUT * HK + k] = __float2half_rn(s);
        }
        if (tid == 0) {
            float s = 0.f;
#pragma unroll
            for (int h = 0; h < HOUT; h++) s += h_bias[h];
            g_hbsum = s;
        }
    } else {
        int i = (bid - 1505) * 256 + tid;
        ((float4*)g_lk)[i] = make_float4(0.f, 0.f, 0.f, 0.f);
    }
}

// ---------------- smem geometry ----------------------------------------------
#define SP   40
#define ABY  (128 * SP * 2)     // 10240 B (128-row array)
#define BBY  (256 * SP * 2)     // 20480 B (256-row array)
#define STG2 (2 * ABY)          // proj stage
#define SMB2 (2 * STG2)         // proj total
#define ASTG (ABY + BBY)        // att stage: A(128) + B(256)
#define ASMB (3 * ASTG)         // 92160 (att: 3-stage)

// ---------------- merged proj GEMM (mode = blockIdx.z), 2-stage --------------
__global__ __launch_bounds__(256, 2) void proj_kernel(
    const float* __restrict__ bv, const float* __restrict__ bq) {
    extern __shared__ char smem[];
    const uint32_t sb = smem_u32(smem);
    const int tid = threadIdx.x;
    const int lane = tid & 31;
    const int wid = tid >> 5;
    const int wm = wid >> 2, wn = wid & 3;
    const int mode = blockIdx.z;
    const int KD = mode ? QD : VD;
    const int CH = KD / 32;
    const int m0 = blockIdx.y * 128;
    const int n0 = blockIdx.x * 128;

    const __half* Agh = mode ? g_qsh : g_vsh;
    const __half* Bgh = mode ? g_wqh : g_wvh;
    const float* bias = mode ? bq : bv;

    const int arow = wm * 64 + (lane & 15);
    const int acol = (lane & 16) ? 8 : 0;
    const uint32_t aoff = (uint32_t)(arow * SP + acol) * 2;
    const int brow = wn * 32 + (lane & 7) + ((lane & 16) ? 8 : 0);
    const int bcol = (lane & 8) ? 8 : 0;
    const uint32_t boff = (uint32_t)(brow * SP + bcol) * 2;

    float acc[4][4][4];
#pragma unroll
    for (int i = 0; i < 4; i++)
#pragma unroll
        for (int j = 0; j < 4; j++)
#pragma unroll
            for (int e = 0; e < 4; e++) acc[i][j][e] = 0.f;

    auto cp_chunk = [&](int c) {
        int k0 = c * 32;
        uint32_t stg = sb + (uint32_t)(c & 1) * STG2;
#pragma unroll
        for (int j = 0; j < 4; j++) {
            int u = tid + j * 256;
            int arr = u >> 9;
            int r = (u >> 2) & 127;
            int seg = u & 3;
            uint32_t dst = stg + (uint32_t)arr * ABY + r * (SP * 2) + seg * 16;
            const __half* src = (arr == 0)
                ? (Agh + (size_t)(m0 + r) * KD + k0 + seg * 8)
                : (Bgh + (size_t)(n0 + r) * KD + k0 + seg * 8);
            CP16(dst, src);
        }
    };

    cp_chunk(0);
    CP_COMMIT();

    for (int c = 0; c < CH; ++c) {
        CP_WAIT0();
        __syncthreads();
        if (c + 1 < CH) { cp_chunk(c + 1); CP_COMMIT(); }

        uint32_t stg = sb + (uint32_t)(c & 1) * STG2;
        uint32_t aAh = stg + aoff;
        uint32_t aBh = stg + ABY + boff;
#pragma unroll
        for (int ks = 0; ks < 2; ks++) {
            uint32_t ah[4][4];
#pragma unroll
            for (int mi = 0; mi < 4; mi++)
                LDMX4(ah[mi], aAh + mi * (16 * SP * 2) + ks * 32);
            uint32_t bh[2][4];
#pragma unroll
            for (int np = 0; np < 2; np++)
                LDMX4(bh[np], aBh + np * (16 * SP * 2) + ks * 32);
#pragma unroll
            for (int mi = 0; mi < 4; mi++)
#pragma unroll
                for (int nj = 0; nj < 4; nj++) {
                    uint32_t b0h = bh[nj >> 1][(nj & 1) * 2];
                    uint32_t b1h = bh[nj >> 1][(nj & 1) * 2 + 1];
                    MMA16816(acc[mi][nj], ah[mi], b0h, b1h);
                }
        }
    }

    const int gid = lane >> 2, tig = lane & 3;
#pragma unroll
    for (int mi = 0; mi < 4; mi++) {
#pragma unroll
        for (int nj = 0; nj < 4; nj++) {
            int row = m0 + wm * 64 + mi * 16 + gid;
            int col = n0 + wn * 32 + nj * 8 + tig * 2;
            float b0 = bias[col], b1 = bias[col + 1];
            float v0 = fmaxf(acc[mi][nj][0] + b0, 0.f);
            float v1 = fmaxf(acc[mi][nj][1] + b1, 0.f);
            float v2 = fmaxf(acc[mi][nj][2] + b0, 0.f);
            float v3 = fmaxf(acc[mi][nj][3] + b1, 0.f);
            size_t o0 = (size_t)row * HK + col;
            size_t o1 = (size_t)(row + 8) * HK + col;
            __half* dst = mode ? g_qh : g_vh;
            *(uint32_t*)(dst + o0) = pack2h(v0, v1);
            *(uint32_t*)(dst + o1) = pack2h(v2, v3);
        }
    }
}

// ---------------- att GEMM: 128x256 tile, A = v_h cp.async, B = q_h*w --------
// Block: 256 thr (8 warps, 2x4), warp tile 64x64, 9 "heads" (hz==8 -> S fp16).
__global__ __launch_bounds__(256, 1) void att_kernel(
    const float* __restrict__ h_bias, float* __restrict__ attout) {
    extern __shared__ char smem[];
    const uint32_t sb = smem_u32(smem);
    const int tid = threadIdx.x;
    const int lane = tid & 31;
    const int wid = tid >> 5;
    const int wm = wid >> 2, wn = wid & 3;
    const int CH = HK / 32;

    const int bz = blockIdx.z / 9;
    const int hz = blockIdx.z - bz * 9;
    const int m0 = blockIdx.y * 128;

    const __half* Ap = g_vh + (size_t)bz * VN * HK;
    const __half* Wrow = g_hwh + hz * HK;
    const __half* Qh = g_qh + (size_t)bz * QN * HK;

    const int arow = wm * 64 + (lane & 15);
    const int acol = (lane & 16) ? 8 : 0;
    const uint32_t aoff = (uint32_t)(arow * SP + acol) * 2;
    const int brow = wn * 64 + (lane & 7) + ((lane & 16) ? 8 : 0);
    const int bcol = (lane & 8) ? 8 : 0;
    const uint32_t boff = (uint32_t)(brow * SP + bcol) * 2;

    float acc[4][8][4];
#pragma unroll
    for (int i = 0; i < 4; i++)
#pragma unroll
        for (int j = 0; j < 8; j++)
#pragma unroll
            for (int e = 0; e < 4; e++) acc[i][j][e] = 0.f;

    uint4 rb[4];

    auto cpA = [&](int c) {
        int k0 = c * 32;
        uint32_t stg = sb + (uint32_t)(c % 3) * ASTG;
#pragma unroll
        for (int j = 0; j < 2; j++) {
            int u = tid + j * 256;
            int r = u >> 2, seg = u & 3;
            uint32_t dst = stg + r * (SP * 2) + seg * 16;
            CP16(dst, Ap + (size_t)(m0 + r) * HK + k0 + seg * 8);
        }
    };
    auto ldgB = [&](int c) {
        int k0 = c * 32;
#pragma unroll
        for (int i = 0; i < 4; i++) {
            int idx = tid + i * 256;
            int r = idx >> 2, seg = idx & 3;
            rb[i] = *(const uint4*)(Qh + (size_t)r * HK + k0 + seg * 8);
        }
    };
    auto stsB = [&](int c) {
        int k0 = c * 32;
        char* st = smem + (c % 3) * ASTG + ABY;
#pragma unroll
        for (int i = 0; i < 4; i++) {
            int idx = tid + i * 256;
            int r = idx >> 2, seg = idx & 3;
            uint4 w = *(const uint4*)(Wrow + k0 + seg * 8);
            uint4 a = rb[i];
            __half2 r0 = __hmul2(*(__half2*)&a.x, *(__half2*)&w.x);
            __half2 r1 = __hmul2(*(__half2*)&a.y, *(__half2*)&w.y);
            __half2 r2 = __hmul2(*(__half2*)&a.z, *(__half2*)&w.z);
            __half2 r3 = __hmul2(*(__half2*)&a.w, *(__half2*)&w.w);
            uint4 o;
            o.x = *(uint32_t*)&r0; o.y = *(uint32_t*)&r1;
            o.z = *(uint32_t*)&r2; o.w = *(uint32_t*)&r3;
            *(uint4*)(st + (uint32_t)r * (SP * 2) + seg * 16) = o;
        }
    };

    cpA(0);
    CP_COMMIT();
    cpA(1);
    CP_COMMIT();
    ldgB(0);

    for (int c = 0; c < CH; ++c) {
        CP_WAIT1();
        stsB(c);
        __syncthreads();
        if (c + 1 < CH) ldgB(c + 1);
        if (c + 2 < CH) { cpA(c + 2); CP_COMMIT(); }

        uint32_t stg = sb + (uint32_t)(c % 3) * ASTG;
        uint32_t aAh = stg + aoff;
        uint32_t aBh = stg + ABY + boff;
#pragma unroll
        for (int ks = 0; ks < 2; ks++) {
            uint32_t ah[4][4];
#pragma unroll
            for (int mi = 0; mi < 4; mi++)
                LDMX4(ah[mi], aAh + mi * (16 * SP * 2) + ks * 32);
            uint32_t bh[4][4];
#pragma unroll
            for (int np = 0; np < 4; np++)
                LDMX4(bh[np], aBh + np * (16 * SP * 2) + ks * 32);
#pragma unroll
            for (int mi = 0; mi < 4; mi++)
#pragma unroll
                for (int nj = 0; nj < 8; nj++) {
                    uint32_t b0h = bh[nj >> 1][(nj & 1) * 2];
                    uint32_t b1h = bh[nj >> 1][(nj & 1) * 2 + 1];
                    MMA16816(acc[mi][nj], ah[mi], b0h, b1h);
                }
        }
    }

    const int gid = lane >> 2, tig = lane & 3;
    float NI = __int_as_float(0xff800000);
    if (hz < 8) {
        float hb = h_bias[hz];
        float* dst = attout + (((size_t)bz * HOUT + hz) * VN + m0) * QN;
#pragma unroll
        for (int mi = 0; mi < 4; mi++) {
#pragma unroll
            for (int nj = 0; nj < 8; nj++) {
                int rl = wm * 64 + mi * 16 + gid;
                int cl = wn * 64 + nj * 8 + tig * 2;
                bool vm0 = g_vmask[bz * VN + m0 + rl] != 0;
                bool vm1 = g_vmask[bz * VN + m0 + rl + 8] != 0;
                bool qm0 = g_qmask[bz * QN + cl] != 0;
                bool qm1 = g_qmask[bz * QN + cl + 1] != 0;
                float v0 = (vm0 || qm0) ? NI : acc[mi][nj][0] + hb;
                float v1 = (vm0 || qm1) ? NI : acc[mi][nj][1] + hb;
                float v2 = (vm1 || qm0) ? NI : acc[mi][nj][2] + hb;
                float v3 = (vm1 || qm1) ? NI : acc[mi][nj][3] + hb;
                *(float2*)(dst + (size_t)rl * QN + cl) = make_float2(v0, v1);
                *(float2*)(dst + (size_t)(rl + 8) * QN + cl) = make_float2(v2, v3);
            }
        }
    } else {
        float hb = g_hbsum;
        __half* dh = g_ssh + ((size_t)bz * VN + m0) * QN;
#pragma unroll
        for (int mi = 0; mi < 4; mi++) {
#pragma unroll
            for (int nj = 0; nj < 8; nj++) {
                int rl = wm * 64 + mi * 16 + gid;
                int cl = wn * 64 + nj * 8 + tig * 2;
                bool vm0 = g_vmask[bz * VN + m0 + rl] != 0;
                bool vm1 = g_vmask[bz * VN + m0 + rl + 8] != 0;
                bool qm0 = g_qmask[bz * QN + cl] != 0;
                bool qm1 = g_qmask[bz * QN + cl + 1] != 0;
                float s0 = (vm0 || qm0) ? NI : acc[mi][nj][0] + hb;
                float s1 = (vm0 || qm1) ? NI : acc[mi][nj][1] + hb;
                float s2 = (vm1 || qm0) ? NI : acc[mi][nj][2] + hb;
                float s3 = (vm1 || qm1) ? NI : acc[mi][nj][3] + hb;
                *(uint32_t*)(dh + (size_t)rl * QN + cl) = pack2h(s0, s1);
                *(uint32_t*)(dh + (size_t)(rl + 8) * QN + cl) = pack2h(s2, s3);
            }
        }
    }
}

// ---------------- pool via MMA, z = mt, 3-stage, S fp16 ----------------------
#define PBSP 136
#define PBBY (32 * PBSP * 2)            // 8704
#define PSTG (ABY + PBBY)               // 18944
#define PSMB (3 * PSTG + 1024)          // 57856

__global__ __launch_bounds__(256, 2) void pool_mma_kernel() {
    extern __shared__ char smem[];
    const uint32_t sb = smem_u32(smem);
    float* red = (float*)(smem + 3 * PSTG);
    const int tid = threadIdx.x;
    const int lane = tid & 31;
    const int wid = tid >> 5;
    const int wm = wid >> 2, wn = wid & 3;
    const int gid = lane >> 2, tig = lane & 3;

    const int bz = blockIdx.y;
    const int k0 = blockIdx.x * 128;
    const int mt = blockIdx.z;

    const __half* Sh = g_ssh + (size_t)bz * VN * QN;
    const __half* Qh = g_qh + (size_t)bz * QN * HK;
    const __half* Vp = g_vh + (size_t)bz * VN * HK;

    const int arow = wm * 64 + (lane & 15);
    const int acol = (lane & 16) ? 8 : 0;
    const uint32_t aoff = (uint32_t)(arow * SP + acol) * 2;
    const int bg = lane >> 3, br = lane & 7;
    const uint32_t btoff = (uint32_t)(((bg & 1) * 8 + br) * PBSP +
                                     wn * 32 + (bg >> 1) * 8) * 2;

    float ps[4][2];
#pragma unroll
    for (int j = 0; j < 4; j++) { ps[j][0] = 0.f; ps[j][1] = 0.f; }

    auto cp_chunk = [&](int c) {
        int q0 = c * 32;
        uint32_t stg = sb + (uint32_t)(c % 3) * PSTG;
#pragma unroll
        for (int j = 0; j < 2; j++) {
            int u = tid + j * 256;
            int r = u >> 2;
            int seg = u & 3;
            uint32_t dst = stg + r * (SP * 2) + seg * 16;
            CP16(dst, Sh + (size_t)(mt * 128 + r) * QN + q0 + seg * 8);
        }
#pragma unroll
        for (int j = 0; j < 2; j++) {
            int u = tid + j * 256;
            int r = (u >> 4) & 31;
            int seg = u & 15;
            uint32_t dst = stg + ABY + r * (PBSP * 2) + seg * 16;
            CP16(dst, Qh + (size_t)(q0 + r) * HK + k0 + seg * 8);
        }
    };

    float acc[4][4][4];
#pragma unroll
    for (int i = 0; i < 4; i++)
#pragma unroll
        for (int j = 0; j < 4; j++)
#pragma unroll
            for (int e = 0; e < 4; e++) acc[i][j][e] = 0.f;

    cp_chunk(0);
    CP_COMMIT();
    cp_chunk(1);
    CP_COMMIT();

    for (int c = 0; c < 8; ++c) {
        CP_WAIT1();
        __syncthreads();
        if (c + 2 < 8) { cp_chunk(c + 2); CP_COMMIT(); }

        uint32_t stg = sb + (uint32_t)(c % 3) * PSTG;
        uint32_t aAh = stg + aoff;
        uint32_t aBh = stg + ABY + btoff;
#pragma unroll
        for (int ks = 0; ks < 2; ks++) {
            uint32_t ah[4][4];
#pragma unroll
            for (int mi = 0; mi < 4; mi++)
                LDMX4(ah[mi], aAh + mi * (16 * SP * 2) + ks * 32);
            uint32_t bh[2][4];
#pragma unroll
            for (int np = 0; np < 2; np++) {
                uint32_t bd = aBh + ks * 16 * (PBSP * 2) + np * 32;
                LDMX4T(bh[np], bd);
            }
#pragma unroll
            for (int mi = 0; mi < 4; mi++)
#pragma unroll
                for (int np = 0; np < 2; np++) {
                    MMA16816(acc[mi][np * 2],     ah[mi], bh[np][0], bh[np][1]);
                    MMA16816(acc[mi][np * 2 + 1], ah[mi], bh[np][2], bh[np][3]);
                }
        }
    }

#pragma unroll
    for (int mi = 0; mi < 4; mi++) {
#pragma unroll
        for (int nj = 0; nj < 4; nj++) {
            int row = mt * 128 + wm * 64 + mi * 16 + gid;
            int col = k0 + wn * 32 + nj * 8 + tig * 2;
            float2 v0 = __half22float2(*(const __half2*)(Vp + (size_t)row * HK + col));
            float2 v1 = __half22float2(*(const __half2*)(Vp + (size_t)(row + 8) * HK + col));
            ps[nj][0] = fmaf(acc[mi][nj][0], v0.x, ps[nj][0]);
            ps[nj][1] = fmaf(acc[mi][nj][1], v0.y, ps[nj][1]);
            ps[nj][0] = fmaf(acc[mi][nj][2], v1.x, ps[nj][0]);
            ps[nj][1] = fmaf(acc[mi][nj][3], v1.y, ps[nj][1]);
        }
    }

#pragma unroll
    for (int nj = 0; nj < 4; nj++)
#pragma unroll
        for (int e = 0; e < 2; e++) {
            float s = ps[nj][e];
            s += __shfl_xor_sync(0xffffffffu, s, 4);
            s += __shfl_xor_sync(0xffffffffu, s, 8);
            s += __shfl_xor_sync(0xffffffffu, s, 16);
            ps[nj][e] = s;
        }
    __syncthreads();
    if (gid == 0) {
#pragma unroll
        for (int nj = 0; nj < 4; nj++) {
            red[wid * 32 + nj * 8 + tig * 2 + 0] = ps[nj][0];
            red[wid * 32 + nj * 8 + tig * 2 + 1] = ps[nj][1];
        }
    }
    __syncthreads();
    if (tid < 128) {
        int wn2 = tid >> 5, cc = tid & 31;
        float s = red[wn2 * 32 + cc] + red[(wn2 + 4) * 32 + cc];
        atomicAdd(g_lk + bz * HK + k0 + tid, s);
    }
}

// ---------------- pool-of-3 + BatchNorm --------------------------------------
__global__ void bn_kernel(const float* __restrict__ gamma, const float* __restrict__ beta,
                          float* __restrict__ out) {
    int c = blockIdx.x * blockDim.x + threadIdx.x;
    if (c >= HD) return;
    float x[B];
    float mu = 0.f;
#pragma unroll
    for (int b = 0; b < B; b++) {
        const float* p = g_lk + b * HK + c * KP;
        x[b] = p[0] + p[1] + p[2];
        mu += x[b];
    }
    mu *= (1.f / B);
    float var = 0.f;
#pragma unroll
    for (int b = 0; b < B; b++) {
        float d = x[b] - mu;
        var = fmaf(d, d, var);
    }
    var *= (1.f / B);
    float scale = rsqrtf(var + 1e-5f) * gamma[c];
    float bet = beta[c];
#pragma unroll
    for (int b = 0; b < B; b++) out[b * HD + c] = (x[b] - mu) * scale + bet;
}

// ---------------- launcher ----------------------------------------------------
extern "C" void kernel_launch(void* const* d_in, const int* in_sizes, int n_in,
                              void* d_out, int out_size) {
    const float* v      = (const float*)d_in[0];
    const float* q      = (const float*)d_in[1];
    const float* Wv     = (const float*)d_in[2];
    const float* bv     = (const float*)d_in[3];
    const float* Wq     = (const float*)d_in[4];
    const float* bq     = (const float*)d_in[5];
    const float* h_mat  = (const float*)d_in[6];
    const float* h_bias = (const float*)d_in[7];
    const float* gamma  = (const float*)d_in[8];
    const float* beta   = (const float*)d_in[9];

    float* out    = (float*)d_out;
    float* logits = out;
    float* att    = out + B * HD;

    cudaFuncSetAttribute(proj_kernel,
                         cudaFuncAttributeMaxDynamicSharedMemorySize, SMB2);
    cudaFuncSetAttribute(att_kernel,
                         cudaFuncAttributeMaxDynamicSharedMemorySize, ASMB);
    cudaFuncSetAttribute(pool_mma_kernel,
                         cudaFuncAttributeMaxDynamicSharedMemorySize, PSMB);

    prep_kernel<<<1529, 256>>>(v, q, Wv, Wq, h_mat, h_bias);
    proj_kernel<<<dim3(HK / 128, (B * VN) / 128, 2), 256, SMB2>>>(bv, bq);
    att_kernel<<<dim3(1, VN / 128, B * 9), 256, ASMB>>>(h_bias, att);
    pool_mma_kernel<<<dim3(HK / 128, B, 2), 256, PSMB>>>();
    bn_kernel<<<(HD + 255) / 256, 256>>>(gamma, beta, logits);
}

// round 16
// speedup vs baseline: 1.1072x; 1.1072x over previous
#include <cuda_runtime.h>
#include <cuda_fp16.h>
#include <stdint.h>
#include <math.h>

#define B    16
#define VN   256
#define QN   256
#define VD   512
#define QD   768
#define HK   1536
#define HOUT 8
#define HD   512
#define KP   3

// ---------------- scratch (device globals) ----------------------------------
__device__ __half g_vh[B * VN * HK];               // v_ fp16
__device__ __half g_qh[B * QN * HK];               // q_ fp16
__device__ __half g_ssh[B * VN * QN];              // S fp16
__device__ float g_lk[B * HK];
__device__ __half g_hwh[(HOUT + 1) * HK];          // 8 head rows + sum row
__device__ float g_hbsum;
__device__ unsigned char g_vmask[B * VN];
__device__ unsigned char g_qmask[B * QN];
__device__ __half g_vsh[B * VN * VD];
__device__ __half g_qsh[B * QN * QD];
__device__ __half g_wvh[HK * VD];
__device__ __half g_wqh[HK * QD];

static __device__ __forceinline__ uint32_t smem_u32(const void* p) {
    uint32_t a;
    asm("{ .reg .u64 t; cvta.to.shared.u64 t, %1; cvt.u32.u64 %0, t; }"
        : "=r"(a) : "l"(p));
    return a;
}

#define LDMX4(d, addr) \
    asm volatile("ldmatrix.sync.aligned.m8n8.x4.shared.b16 {%0,%1,%2,%3}, [%4];" \
                 : "=r"((d)[0]), "=r"((d)[1]), "=r"((d)[2]), "=r"((d)[3]) \
                 : "r"(addr))

#define LDMX4T(d, addr) \
    asm volatile("ldmatrix.sync.aligned.m8n8.x4.trans.shared.b16 {%0,%1,%2,%3}, [%4];" \
                 : "=r"((d)[0]), "=r"((d)[1]), "=r"((d)[2]), "=r"((d)[3]) \
                 : "r"(addr))

#define MMA16816(c, a, b0, b1) \
    asm volatile("mma.sync.aligned.m16n8k16.row.col.f32.f16.f16.f32 " \
                 "{%0,%1,%2,%3}, {%4,%5,%6,%7}, {%8,%9}, {%0,%1,%2,%3};" \
                 : "+f"((c)[0]), "+f"((c)[1]), "+f"((c)[2]), "+f"((c)[3]) \
                 : "r"((a)[0]), "r"((a)[1]), "r"((a)[2]), "r"((a)[3]), \
                   "r"(b0), "r"(b1))

#define CP16(dst, src) \
    asm volatile("cp.async.cg.shared.global [%0], [%1], 16;" \
                 :: "r"(dst), "l"(src))
#define CP_COMMIT() asm volatile("cp.async.commit_group;" ::: "memory")
#define CP_WAIT0()  asm volatile("cp.async.wait_group 0;" ::: "memory")
#define CP_WAIT1()  asm volatile("cp.async.wait_group 1;" ::: "memory")

static __device__ __forceinline__ uint32_t pack2h(float a, float b) {
    __half2 h = __floats2half2_rn(a, b);
    return *(uint32_t*)&h;
}

// ---------------- fused prep -------------------------------------------------
__global__ void prep_kernel(const float* __restrict__ v, const float* __restrict__ q,
                            const float* __restrict__ Wv, const float* __restrict__ Wq,
                            const float* __restrict__ h_mat,
                            const float* __restrict__ h_bias) {
    const int bid = blockIdx.x;
    const int tid = threadIdx.x;
    if (bid < 512) {
        int wid = tid >> 5, lane = tid & 31;
        int row = bid * 8 + wid;
        const float4* src = (const float4*)(v + (size_t)row * VD);
        uint2* dst = (uint2*)(g_vsh + (size_t)row * VD);
        float s = 0.f;
#pragma unroll
        for (int j = 0; j < 4; j++) {
            float4 x = src[j * 32 + lane];
            s += fabsf(x.x) + fabsf(x.y) + fabsf(x.z) + fabsf(x.w);
            uint2 h;
            h.x = pack2h(x.x, x.y);
            h.y = pack2h(x.z, x.w);
            dst[j * 32 + lane] = h;
        }
        for (int o = 16; o; o >>= 1) s += __shfl_xor_sync(0xffffffffu, s, o);
        if (lane == 0) g_vmask[row] = (s == 0.f) ? 1 : 0;
    } else if (bid < 1024) {
        int wid = tid >> 5, lane = tid & 31;
        int row = (bid - 512) * 8 + wid;
        const float4* src = (const float4*)(q + (size_t)row * QD);
        uint2* dst = (uint2*)(g_qsh + (size_t)row * QD);
        float s = 0.f;
#pragma unroll
        for (int j = 0; j < 6; j++) {
            float4 x = src[j * 32 + lane];
            s += fabsf(x.x) + fabsf(x.y) + fabsf(x.z) + fabsf(x.w);
            uint2 h;
            h.x = pack2h(x.x, x.y);
            h.y = pack2h(x.z, x.w);
            dst[j * 32 + lane] = h;
        }
        for (int o = 16; o; o >>= 1) s += __shfl_xor_sync(0xffffffffu, s, o);
        if (lane == 0) g_qmask[row] = (s == 0.f) ? 1 : 0;
    } else if (bid < 1216) {
        int base = (bid - 1024) * 1024;
#pragma unroll
        for (int j = 0; j < 4; j++) {
            int i = base + j * 256 + tid;
            float4 x = ((const float4*)Wv)[i];
            uint2 h;
            h.x = pack2h(x.x, x.y);
            h.y = pack2h(x.z, x.w);
            *(uint2*)(g_wvh + (size_t)i * 4) = h;
        }
    } else if (bid < 1504) {
        int base = (bid - 1216) * 1024;
#pragma unroll
        for (int j = 0; j < 4; j++) {
            int i = base + j * 256 + tid;
            float4 x = ((const float4*)Wq)[i];
            uint2 h;
            h.x = pack2h(x.x, x.y);
            h.y = pack2h(x.z, x.w);
            *(uint2*)(g_wqh + (size_t)i * 4) = h;
        }
    } else if (bid == 1504) {
        for (int k = tid; k < HK; k += 256) {
            float s = 0.f;
#pragma unroll
            for (int h = 0; h < HOUT; h++) {
                float w = h_mat[h * HK + k];
                g_hwh[h * HK + k] = __float2half_rn(w);
                s += w;
            }
            g_hwh[HOUT * HK + k] = __float2half_rn(s);
        }
        if (tid == 0) {
            float s = 0.f;
#pragma unroll
            for (int h = 0; h < HOUT; h++) s += h_bias[h];
            g_hbsum = s;
        }
    } else {
        int i = (bid - 1505) * 256 + tid;
        ((float4*)g_lk)[i] = make_float4(0.f, 0.f, 0.f, 0.f);
    }
}

// ---------------- smem geometry ----------------------------------------------
#define SP   40
#define ABY  (128 * SP * 2)     // 10240 B (128-row, k32 array)
#define STG2 (2 * ABY)          // proj stage
#define SMB2 (2 * STG2)         // proj total
// att: k-chunk 64, stride 72 halves (144 B, ldmatrix conflict-free)
#define SP2  72
#define ABY2 (128 * SP2 * 2)    // 18432 B
#define ASTG (2 * ABY2)         // 36864 per stage (A + B)
#define ASMB (2 * ASTG)         // 73728 (2-stage)

// ---------------- merged proj GEMM (mode = blockIdx.z), 2-stage --------------
__global__ __launch_bounds__(256, 2) void proj_kernel(
    const float* __restrict__ bv, const float* __restrict__ bq) {
    extern __shared__ char smem[];
    const uint32_t sb = smem_u32(smem);
    const int tid = threadIdx.x;
    const int lane = tid & 31;
    const int wid = tid >> 5;
    const int wm = wid >> 2, wn = wid & 3;
    const int mode = blockIdx.z;
    const int KD = mode ? QD : VD;
    const int CH = KD / 32;
    const int m0 = blockIdx.y * 128;
    const int n0 = blockIdx.x * 128;

    const __half* Agh = mode ? g_qsh : g_vsh;
    const __half* Bgh = mode ? g_wqh : g_wvh;
    const float* bias = mode ? bq : bv;

    const int arow = wm * 64 + (lane & 15);
    const int acol = (lane & 16) ? 8 : 0;
    const uint32_t aoff = (uint32_t)(arow * SP + acol) * 2;
    const int brow = wn * 32 + (lane & 7) + ((lane & 16) ? 8 : 0);
    const int bcol = (lane & 8) ? 8 : 0;
    const uint32_t boff = (uint32_t)(brow * SP + bcol) * 2;

    float acc[4][4][4];
#pragma unroll
    for (int i = 0; i < 4; i++)
#pragma unroll
        for (int j = 0; j < 4; j++)
#pragma unroll
            for (int e = 0; e < 4; e++) acc[i][j][e] = 0.f;

    auto cp_chunk = [&](int c) {
        int k0 = c * 32;
        uint32_t stg = sb + (uint32_t)(c & 1) * STG2;
#pragma unroll
        for (int j = 0; j < 4; j++) {
            int u = tid + j * 256;
            int arr = u >> 9;
            int r = (u >> 2) & 127;
            int seg = u & 3;
            uint32_t dst = stg + (uint32_t)arr * ABY + r * (SP * 2) + seg * 16;
            const __half* src = (arr == 0)
                ? (Agh + (size_t)(m0 + r) * KD + k0 + seg * 8)
                : (Bgh + (size_t)(n0 + r) * KD + k0 + seg * 8);
            CP16(dst, src);
        }
    };

    cp_chunk(0);
    CP_COMMIT();

    for (int c = 0; c < CH; ++c) {
        CP_WAIT0();
        __syncthreads();
        if (c + 1 < CH) { cp_chunk(c + 1); CP_COMMIT(); }

        uint32_t stg = sb + (uint32_t)(c & 1) * STG2;
        uint32_t aAh = stg + aoff;
        uint32_t aBh = stg + ABY + boff;
#pragma unroll
        for (int ks = 0; ks < 2; ks++) {
            uint32_t ah[4][4];
#pragma unroll
            for (int mi = 0; mi < 4; mi++)
                LDMX4(ah[mi], aAh + mi * (16 * SP * 2) + ks * 32);
            uint32_t bh[2][4];
#pragma unroll
            for (int np = 0; np < 2; np++)
                LDMX4(bh[np], aBh + np * (16 * SP * 2) + ks * 32);
#pragma unroll
            for (int mi = 0; mi < 4; mi++)
#pragma unroll
                for (int nj = 0; nj < 4; nj++) {
                    uint32_t b0h = bh[nj >> 1][(nj & 1) * 2];
                    uint32_t b1h = bh[nj >> 1][(nj & 1) * 2 + 1];
                    MMA16816(acc[mi][nj], ah[mi], b0h, b1h);
                }
        }
    }

    const int gid = lane >> 2, tig = lane & 3;
#pragma unroll
    for (int mi = 0; mi < 4; mi++) {
#pragma unroll
        for (int nj = 0; nj < 4; nj++) {
            int row = m0 + wm * 64 + mi * 16 + gid;
            int col = n0 + wn * 32 + nj * 8 + tig * 2;
            float b0 = bias[col], b1 = bias[col + 1];
            float v0 = fmaxf(acc[mi][nj][0] + b0, 0.f);
            float v1 = fmaxf(acc[mi][nj][1] + b1, 0.f);
            float v2 = fmaxf(acc[mi][nj][2] + b0, 0.f);
            float v3 = fmaxf(acc[mi][nj][3] + b1, 0.f);
            size_t o0 = (size_t)row * HK + col;
            size_t o1 = (size_t)(row + 8) * HK + col;
            __half* dst = mode ? g_qh : g_vh;
            *(uint32_t*)(dst + o0) = pack2h(v0, v1);
            *(uint32_t*)(dst + o1) = pack2h(v2, v3);
        }
    }
}

// ---------------- att GEMM: 128x128 tile, k-chunk 64, 2-stage ----------------
__global__ __launch_bounds__(256, 2) void att_kernel(
    const float* __restrict__ h_bias, float* __restrict__ attout) {
    extern __shared__ char smem[];
    const uint32_t sb = smem_u32(smem);
    const int tid = threadIdx.x;
    const int lane = tid & 31;
    const int wid = tid >> 5;
    const int wm = wid >> 2, wn = wid & 3;
    const int CH = HK / 64;     // 24

    const int bz = blockIdx.z / 9;
    const int hz = blockIdx.z - bz * 9;
    const int m0 = blockIdx.y * 128;
    const int n0 = blockIdx.x * 128;

    const __half* Ap = g_vh + (size_t)bz * VN * HK;
    const __half* Wrow = g_hwh + hz * HK;
    const __half* Qh = g_qh + (size_t)bz * QN * HK;

    const int arow = wm * 64 + (lane & 15);
    const int acol = (lane & 16) ? 8 : 0;
    const uint32_t aoff = (uint32_t)(arow * SP2 + acol) * 2;
    const int brow = wn * 32 + (lane & 7) + ((lane & 16) ? 8 : 0);
    const int bcol = (lane & 8) ? 8 : 0;
    const uint32_t boff = (uint32_t)(brow * SP2 + bcol) * 2;

    float acc[4][4][4];
#pragma unroll
    for (int i = 0; i < 4; i++)
#pragma unroll
        for (int j = 0; j < 4; j++)
#pragma unroll
            for (int e = 0; e < 4; e++) acc[i][j][e] = 0.f;

    uint4 rb[4];

    // A: cp.async v_h, 16 KB per chunk (128 rows x 64 halves)
    auto cpA = [&](int c) {
        int k0 = c * 64;
        uint32_t stg = sb + (uint32_t)(c & 1) * ASTG;
#pragma unroll
        for (int j = 0; j < 4; j++) {
            int u = tid + j * 256;
            int r = u >> 3, seg = u & 7;
            uint32_t dst = stg + r * (SP2 * 2) + seg * 16;
            CP16(dst, Ap + (size_t)(m0 + r) * HK + k0 + seg * 8);
        }
    };
    // B: LDG q_h -> regs (128 rows x 64 halves)
    auto ldgB = [&](int c) {
        int k0 = c * 64;
#pragma unroll
        for (int i = 0; i < 4; i++) {
            int idx = tid + i * 256;
            int r = idx >> 3, seg = idx & 7;
            rb[i] = *(const uint4*)(Qh + (size_t)(n0 + r) * HK + k0 + seg * 8);
        }
    };
    // fold w into B, store to smem
    auto stsB = [&](int c) {
        int k0 = c * 64;
        char* st = smem + (c & 1) * ASTG + ABY2;
#pragma unroll
        for (int i = 0; i < 4; i++) {
            int idx = tid + i * 256;
            int r = idx >> 3, seg = idx & 7;
            uint4 w = *(const uint4*)(Wrow + k0 + seg * 8);
            uint4 a = rb[i];
            __half2 r0 = __hmul2(*(__half2*)&a.x, *(__half2*)&w.x);
            __half2 r1 = __hmul2(*(__half2*)&a.y, *(__half2*)&w.y);
            __half2 r2 = __hmul2(*(__half2*)&a.z, *(__half2*)&w.z);
            __half2 r3 = __hmul2(*(__half2*)&a.w, *(__half2*)&w.w);
            uint4 o;
            o.x = *(uint32_t*)&r0; o.y = *(uint32_t*)&r1;
            o.z = *(uint32_t*)&r2; o.w = *(uint32_t*)&r3;
            *(uint4*)(st + (uint32_t)r * (SP2 * 2) + seg * 16) = o;
        }
    };

    cpA(0);
    CP_COMMIT();
    ldgB(0);

    for (int c = 0; c < CH; ++c) {
        CP_WAIT0();
        stsB(c);
        __syncthreads();
        if (c + 1 < CH) { cpA(c + 1); CP_COMMIT(); ldgB(c + 1); }

        uint32_t stg = sb + (uint32_t)(c & 1) * ASTG;
        uint32_t aAh = stg + aoff;
        uint32_t aBh = stg + ABY2 + boff;
#pragma unroll
        for (int ks = 0; ks < 4; ks++) {
            uint32_t ah[4][4];
#pragma unroll
            for (int mi = 0; mi < 4; mi++)
                LDMX4(ah[mi], aAh + mi * (16 * SP2 * 2) + ks * 32);
            uint32_t bh[2][4];
#pragma unroll
            for (int np = 0; np < 2; np++)
                LDMX4(bh[np], aBh + np * (16 * SP2 * 2) + ks * 32);
#pragma unroll
            for (int mi = 0; mi < 4; mi++)
#pragma unroll
                for (int nj = 0; nj < 4; nj++) {
                    uint32_t b0h = bh[nj >> 1][(nj & 1) * 2];
                    uint32_t b1h = bh[nj >> 1][(nj & 1) * 2 + 1];
                    MMA16816(acc[mi][nj], ah[mi], b0h, b1h);
                }
        }
    }

    const int gid = lane >> 2, tig = lane & 3;
    float NI = __int_as_float(0xff800000);
    if (hz < 8) {
        float hb = h_bias[hz];
        float* dst = attout + (((size_t)bz * HOUT + hz) * VN + m0) * QN + n0;
#pragma unroll
        for (int mi = 0; mi < 4; mi++) {
#pragma unroll
            for (int nj = 0; nj < 4; nj++) {
                int rl = wm * 64 + mi * 16 + gid;
                int cl = wn * 32 + nj * 8 + tig * 2;
                bool vm0 = g_vmask[bz * VN + m0 + rl] != 0;
                bool vm1 = g_vmask[bz * VN + m0 + rl + 8] != 0;
                bool qm0 = g_qmask[bz * QN + n0 + cl] != 0;
                bool qm1 = g_qmask[bz * QN + n0 + cl + 1] != 0;
                float v0 = (vm0 || qm0) ? NI : acc[mi][nj][0] + hb;
                float v1 = (vm0 || qm1) ? NI : acc[mi][nj][1] + hb;
                float v2 = (vm1 || qm0) ? NI : acc[mi][nj][2] + hb;
                float v3 = (vm1 || qm1) ? NI : acc[mi][nj][3] + hb;
                *(float2*)(dst + (size_t)rl * QN + cl) = make_float2(v0, v1);
                *(float2*)(dst + (size_t)(rl + 8) * QN + cl) = make_float2(v2, v3);
            }
        }
    } else {
        float hb = g_hbsum;
        __half* dh = g_ssh + ((size_t)bz * VN + m0) * QN + n0;
#pragma unroll
        for (int mi = 0; mi < 4; mi++) {
#pragma unroll
            for (int nj = 0; nj < 4; nj++) {
                int rl = wm * 64 + mi * 16 + gid;
                int cl = wn * 32 + nj * 8 + tig * 2;
                bool vm0 = g_vmask[bz * VN + m0 + rl] != 0;
                bool vm1 = g_vmask[bz * VN + m0 + rl + 8] != 0;
                bool qm0 = g_qmask[bz * QN + n0 + cl] != 0;
                bool qm1 = g_qmask[bz * QN + n0 + cl + 1] != 0;
                float s0 = (vm0 || qm0) ? NI : acc[mi][nj][0] + hb;
                float s1 = (vm0 || qm1) ? NI : acc[mi][nj][1] + hb;
                float s2 = (vm1 || qm0) ? NI : acc[mi][nj][2] + hb;
                float s3 = (vm1 || qm1) ? NI : acc[mi][nj][3] + hb;
                *(uint32_t*)(dh + (size_t)rl * QN + cl) = pack2h(s0, s1);
                *(uint32_t*)(dh + (size_t)(rl + 8) * QN + cl) = pack2h(s2, s3);
            }
        }
    }
}

// ---------------- pool via MMA, z = mt, 3-stage, S fp16 ----------------------
#define PBSP 136
#define PBBY (32 * PBSP * 2)            // 8704
#define PSTG (ABY + PBBY)               // 18944
#define PSMB (3 * PSTG + 1024)          // 57856

__global__ __launch_bounds__(256, 2) void pool_mma_kernel() {
    extern __shared__ char smem[];
    const uint32_t sb = smem_u32(smem);
    float* red = (float*)(smem + 3 * PSTG);
    const int tid = threadIdx.x;
    const int lane = tid & 31;
    const int wid = tid >> 5;
    const int wm = wid >> 2, wn = wid & 3;
    const int gid = lane >> 2, tig = lane & 3;

    const int bz = blockIdx.y;
    const int k0 = blockIdx.x * 128;
    const int mt = blockIdx.z;

    const __half* Sh = g_ssh + (size_t)bz * VN * QN;
    const __half* Qh = g_qh + (size_t)bz * QN * HK;
    const __half* Vp = g_vh + (size_t)bz * VN * HK;

    const int arow = wm * 64 + (lane & 15);
    const int acol = (lane & 16) ? 8 : 0;
    const uint32_t aoff = (uint32_t)(arow * SP + acol) * 2;
    const int bg = lane >> 3, br = lane & 7;
    const uint32_t btoff = (uint32_t)(((bg & 1) * 8 + br) * PBSP +
                                     wn * 32 + (bg >> 1) * 8) * 2;

    float ps[4][2];
#pragma unroll
    for (int j = 0; j < 4; j++) { ps[j][0] = 0.f; ps[j][1] = 0.f; }

    auto cp_chunk = [&](int c) {
        int q0 = c * 32;
        uint32_t stg = sb + (uint32_t)(c % 3) * PSTG;
#pragma unroll
        for (int j = 0; j < 2; j++) {
            int u = tid + j * 256;
            int r = u >> 2;
            int seg = u & 3;
            uint32_t dst = stg + r * (SP * 2) + seg * 16;
            CP16(dst, Sh + (size_t)(mt * 128 + r) * QN + q0 + seg * 8);
        }
#pragma unroll
        for (int j = 0; j < 2; j++) {
            int u = tid + j * 256;
            int r = (u >> 4) & 31;
            int seg = u & 15;
            uint32_t dst = stg + ABY + r * (PBSP * 2) + seg * 16;
            CP16(dst, Qh + (size_t)(q0 + r) * HK + k0 + seg * 8);
        }
    };

    float acc[4][4][4];
#pragma unroll
    for (int i = 0; i < 4; i++)
#pragma unroll
        for (int j = 0; j < 4; j++)
#pragma unroll
            for (int e = 0; e < 4; e++) acc[i][j][e] = 0.f;

    cp_chunk(0);
    CP_COMMIT();
    cp_chunk(1);
    CP_COMMIT();

    for (int c = 0; c < 8; ++c) {
        CP_WAIT1();
        __syncthreads();
        if (c + 2 < 8) { cp_chunk(c + 2); CP_COMMIT(); }

        uint32_t stg = sb + (uint32_t)(c % 3) * PSTG;
        uint32_t aAh = stg + aoff;
        uint32_t aBh = stg + ABY + btoff;
#pragma unroll
        for (int ks = 0; ks < 2; ks++) {
            uint32_t ah[4][4];
#pragma unroll
            for (int mi = 0; mi < 4; mi++)
                LDMX4(ah[mi], aAh + mi * (16 * SP * 2) + ks * 32);
            uint32_t bh[2][4];
#pragma unroll
            for (int np = 0; np < 2; np++) {
                uint32_t bd = aBh + ks * 16 * (PBSP * 2) + np * 32;
                LDMX4T(bh[np], bd);
            }
#pragma unroll
            for (int mi = 0; mi < 4; mi++)
#pragma unroll
                for (int np = 0; np < 2; np++) {
                    MMA16816(acc[mi][np * 2],     ah[mi], bh[np][0], bh[np][1]);
                    MMA16816(acc[mi][np * 2 + 1], ah[mi], bh[np][2], bh[np][3]);
                }
        }
    }

#pragma unroll
    for (int mi = 0; mi < 4; mi++) {
#pragma unroll
        for (int nj = 0; nj < 4; nj++) {
            int row = mt * 128 + wm * 64 + mi * 16 + gid;
            int col = k0 + wn * 32 + nj * 8 + tig * 2;
            float2 v0 = __half22float2(*(const __half2*)(Vp + (size_t)row * HK + col));
            float2 v1 = __half22float2(*(const __half2*)(Vp + (size_t)(row + 8) * HK + col));
            ps[nj][0] = fmaf(acc[mi][nj][0], v0.x, ps[nj][0]);
            ps[nj][1] = fmaf(acc[mi][nj][1], v0.y, ps[nj][1]);
            ps[nj][0] = fmaf(acc[mi][nj][2], v1.x, ps[nj][0]);
            ps[nj][1] = fmaf(acc[mi][nj][3], v1.y, ps[nj][1]);
        }
    }

#pragma unroll
    for (int nj = 0; nj < 4; nj++)
#pragma unroll
        for (int e = 0; e < 2; e++) {
            float s = ps[nj][e];
            s += __shfl_xor_sync(0xffffffffu, s, 4);
            s += __shfl_xor_sync(0xffffffffu, s, 8);
            s += __shfl_xor_sync(0xffffffffu, s, 16);
            ps[nj][e] = s;
        }
    __syncthreads();
    if (gid == 0) {
#pragma unroll
        for (int nj = 0; nj < 4; nj++) {
            red[wid * 32 + nj * 8 + tig * 2 + 0] = ps[nj][0];
            red[wid * 32 + nj * 8 + tig * 2 + 1] = ps[nj][1];
        }
    }
    __syncthreads();
    if (tid < 128) {
        int wn2 = tid >> 5, cc = tid & 31;
        float s = red[wn2 * 32 + cc] + red[(wn2 + 4) * 32 + cc];
        atomicAdd(g_lk + bz * HK + k0 + tid, s);
    }
}

// ---------------- pool-of-3 + BatchNorm --------------------------------------
__global__ void bn_kernel(const float* __restrict__ gamma, const float* __restrict__ beta,
                          float* __restrict__ out) {
    int c = blockIdx.x * blockDim.x + threadIdx.x;
    if (c >= HD) return;
    float x[B];
    float mu = 0.f;
#pragma unroll
    for (int b = 0; b < B; b++) {
        const float* p = g_lk + b * HK + c * KP;
        x[b] = p[0] + p[1] + p[2];
        mu += x[b];
    }
    mu *= (1.f / B);
    float var = 0.f;
#pragma unroll
    for (int b = 0; b < B; b++) {
        float d = x[b] - mu;
        var = fmaf(d, d, var);
    }
    var *= (1.f / B);
    float scale = rsqrtf(var + 1e-5f) * gamma[c];
    float bet = beta[c];
#pragma unroll
    for (int b = 0; b < B; b++) out[b * HD + c] = (x[b] - mu) * scale + bet;
}

// ---------------- launcher ----------------------------------------------------
extern "C" void kernel_launch(void* const* d_in, const int* in_sizes, int n_in,
                              void* d_out, int out_size) {
    const float* v      = (const float*)d_in[0];
    const float* q      = (const float*)d_in[1];
    const float* Wv     = (const float*)d_in[2];
    const float* bv     = (const float*)d_in[3];
    const float* Wq     = (const float*)d_in[4];
    const float* bq     = (const float*)d_in[5];
    const float* h_mat  = (const float*)d_in[6];
    const float* h_bias = (const float*)d_in[7];
    const float* gamma  = (const float*)d_in[8];
    const float* beta   = (const float*)d_in[9];

    float* out    = (float*)d_out;
    float* logits = out;
    float* att    = out + B * HD;

    cudaFuncSetAttribute(proj_kernel,
                         cudaFuncAttributeMaxDynamicSharedMemorySize, SMB2);
    cudaFuncSetAttribute(att_kernel,
                         cudaFuncAttributeMaxDynamicSharedMemorySize, ASMB);
    cudaFuncSetAttribute(pool_mma_kernel,
                         cudaFuncAttributeMaxDynamicSharedMemorySize, PSMB);

    prep_kernel<<<1529, 256>>>(v, q, Wv, Wq, h_mat, h_bias);
    proj_kernel<<<dim3(HK / 128, (B * VN) / 128, 2), 256, SMB2>>>(bv, bq);
    att_kernel<<<dim3(QN / 128, VN / 128, B * 9), 256, ASMB>>>(h_bias, att);
    pool_mma_kernel<<<dim3(HK / 128, B, 2), 256, PSMB>>>();
    bn_kernel<<<(HD + 255) / 256, 256>>>(gamma, beta, logits);
}